// round 1
// baseline (speedup 1.0000x reference)
#include <cuda_runtime.h>
#include <math.h>

// ---------------- problem constants ----------------
#define DHID   512
#define NHEAD  8
#define DH     64
#define LAYERS 6
#define BB     16
#define TT     32
#define NTOK   64          // 8x8 spatial tokens
#define KCONV  576         // 3*3*8*8
#define BT     512         // BB*TT
#define MCONV  32768       // BT*NTOK

// ---------------- device scratch (no allocs allowed) ----------------
__device__ float g_wT[KCONV * DHID];          // conv weight transposed [K,N]
__device__ float g_patches[MCONV * KCONV];    // im2col
__device__ float g_tok[MCONV * DHID];         // conv output tokens
__device__ float g_film[BT * 2 * DHID];       // gamma,beta per (b,t)
__device__ float g_h[BT * DHID];              // temporal sequence
__device__ float g_xln[BT * DHID];
__device__ float g_kqv[BT * 3 * DHID];
__device__ float g_attn[BT * DHID];
__device__ float g_mlp[BT * 4 * DHID];

// ---------------- helpers ----------------
__device__ __forceinline__ float warp_sum(float v) {
#pragma unroll
    for (int o = 16; o; o >>= 1) v += __shfl_xor_sync(0xffffffffu, v, o);
    return v;
}
__device__ __forceinline__ float warp_max(float v) {
#pragma unroll
    for (int o = 16; o; o >>= 1) v = fmaxf(v, __shfl_xor_sync(0xffffffffu, v, o));
    return v;
}
// 256-thread block sum; safe to call repeatedly (sync after read)
__device__ __forceinline__ float block_sum_256(float v, float* sbuf) {
    int lane = threadIdx.x & 31, wid = threadIdx.x >> 5;
    v = warp_sum(v);
    if (lane == 0) sbuf[wid] = v;
    __syncthreads();
    float r = sbuf[0];
#pragma unroll
    for (int w = 1; w < 8; w++) r += sbuf[w];
    __syncthreads();
    return r;
}

// ---------------- conv weight transpose [512,576] -> [576,512] ----------------
__global__ void transpose_w_kernel(const float* __restrict__ w, float* __restrict__ wT) {
    int idx = blockIdx.x * 256 + threadIdx.x;
    if (idx >= DHID * KCONV) return;
    int d = idx / KCONV, k = idx % KCONV;
    wT[k * DHID + d] = w[idx];
}

// ---------------- im2col (causal time pad 2) ----------------
__global__ void im2col_kernel(const float* __restrict__ x, float* __restrict__ p) {
    int idx = blockIdx.x * 256 + threadIdx.x;
    if (idx >= MCONV * KCONV) return;
    int kcol = idx % KCONV;
    int row  = idx / KCONV;
    int n  = row & 63;           // spatial token
    int bt = row >> 6;
    int t  = bt & 31;
    int b  = bt >> 5;
    int hn = n >> 3, wn = n & 7;
    int pw = kcol & 7;
    int ph = (kcol >> 3) & 7;
    int kt = (kcol >> 6) % 3;
    int c  = kcol / 192;
    int tt = t + kt - 2;
    float v = 0.f;
    if (tt >= 0) {
        v = x[((((b * 32 + tt) * 3 + c) * 64) + hn * 8 + ph) * 64 + wn * 8 + pw];
    }
    p[idx] = v;
}

// ---------------- generic tiled fp32 GEMM ----------------
// C[M,N] = epi( A[M,K] * B[K,N] + bias[N] )
// epi 0: none   1: exact GELU   2: C = res + scale[0]*(acc+bias)
__global__ void gemm_kernel(const float* __restrict__ A, const float* __restrict__ Bm,
                            const float* __restrict__ bias, float* C,
                            int M, int N, int K, int epi,
                            const float* res, const float* scale) {
    __shared__ float As[16][65];
    __shared__ float Bs[16][64];
    int bm = blockIdx.y * 64, bn = blockIdx.x * 64;
    int tid = threadIdx.x;
    int tx = tid & 15, ty = tid >> 4;
    float acc[4][4];
#pragma unroll
    for (int i = 0; i < 4; i++)
#pragma unroll
        for (int j = 0; j < 4; j++) acc[i][j] = 0.f;

    const float* Ab = A + (long)bm * K;
    for (int k0 = 0; k0 < K; k0 += 16) {
        {
            int col = tid & 15, row = tid >> 4;
#pragma unroll
            for (int r = 0; r < 4; r++)
                As[col][row + r * 16] = Ab[(long)(row + r * 16) * K + k0 + col];
        }
        {
            int col = tid & 63, row = tid >> 6;
#pragma unroll
            for (int r = 0; r < 4; r++)
                Bs[row + r * 4][col] = Bm[(long)(k0 + row + r * 4) * N + bn + col];
        }
        __syncthreads();
#pragma unroll
        for (int kk = 0; kk < 16; kk++) {
            float a0 = As[kk][ty * 4 + 0];
            float a1 = As[kk][ty * 4 + 1];
            float a2 = As[kk][ty * 4 + 2];
            float a3 = As[kk][ty * 4 + 3];
            float4 b4 = *(const float4*)&Bs[kk][tx * 4];
            acc[0][0] += a0 * b4.x; acc[0][1] += a0 * b4.y; acc[0][2] += a0 * b4.z; acc[0][3] += a0 * b4.w;
            acc[1][0] += a1 * b4.x; acc[1][1] += a1 * b4.y; acc[1][2] += a1 * b4.z; acc[1][3] += a1 * b4.w;
            acc[2][0] += a2 * b4.x; acc[2][1] += a2 * b4.y; acc[2][2] += a2 * b4.z; acc[2][3] += a2 * b4.w;
            acc[3][0] += a3 * b4.x; acc[3][1] += a3 * b4.y; acc[3][2] += a3 * b4.z; acc[3][3] += a3 * b4.w;
        }
        __syncthreads();
    }
    float sc = (epi == 2) ? scale[0] : 0.f;
#pragma unroll
    for (int i = 0; i < 4; i++) {
        int row = bm + ty * 4 + i;
#pragma unroll
        for (int j = 0; j < 4; j++) {
            int col = bn + tx * 4 + j;
            float v = acc[i][j] + bias[col];
            if (epi == 1) v = 0.5f * v * (1.f + erff(v * 0.70710678118654752f));
            else if (epi == 2) v = res[(long)row * N + col] + sc * v;
            C[(long)row * N + col] = v;
        }
    }
}

// ---------------- fused token LN + FiLM + spatial mean ----------------
// tok [MCONV, D] -> h [BT, D]
__global__ void tok_reduce_kernel(const float* __restrict__ tok, const float* __restrict__ tg,
                                  const float* __restrict__ tb, const float* __restrict__ film,
                                  float* __restrict__ h) {
    __shared__ float accs[8][DHID];   // 16 KB
    int bt = blockIdx.x;
    int wid = threadIdx.x >> 5, lane = threadIdx.x & 31;
    float acc[16];
#pragma unroll
    for (int i = 0; i < 16; i++) acc[i] = 0.f;

    const float* gb = film + bt * (2 * DHID);
    for (int n = wid; n < NTOK; n += 8) {
        const float* row = tok + (long)(bt * NTOK + n) * DHID;
        float v[16];
        float s = 0.f;
#pragma unroll
        for (int i = 0; i < 16; i++) { v[i] = row[i * 32 + lane]; s += v[i]; }
        s = warp_sum(s);
        float mu = s * (1.f / 512.f);
        float vs = 0.f;
#pragma unroll
        for (int i = 0; i < 16; i++) { float d = v[i] - mu; vs += d * d; }
        vs = warp_sum(vs);
        float rstd = rsqrtf(vs * (1.f / 512.f) + 1e-5f);
#pragma unroll
        for (int i = 0; i < 16; i++) {
            int d = i * 32 + lane;
            float ln = (v[i] - mu) * rstd * tg[d] + tb[d];
            float ga = gb[d], be = gb[DHID + d];
            acc[i] += (1.f + 0.5f * ga) * ln + 0.5f * be;
        }
    }
#pragma unroll
    for (int i = 0; i < 16; i++) accs[wid][i * 32 + lane] = acc[i];
    __syncthreads();
    for (int d = threadIdx.x; d < DHID; d += 256) {
        float s = 0.f;
#pragma unroll
        for (int w = 0; w < 8; w++) s += accs[w][d];
        h[bt * DHID + d] = s * (1.f / 64.f);
    }
}

// ---------------- LayerNorm: [ntok, 512] ----------------
__global__ void ln_kernel(const float* __restrict__ in, const float* __restrict__ g,
                          const float* __restrict__ b, float* __restrict__ out) {
    __shared__ float sbuf[8];
    int tok = blockIdx.x, tid = threadIdx.x;
    const float* row = in + tok * DHID;
    float v0 = row[tid], v1 = row[tid + 256];
    float sum = block_sum_256(v0 + v1, sbuf);
    float mu = sum * (1.f / 512.f);
    float d0 = v0 - mu, d1 = v1 - mu;
    float vs = block_sum_256(d0 * d0 + d1 * d1, sbuf);
    float rstd = rsqrtf(vs * (1.f / 512.f) + 1e-5f);
    out[tok * DHID + tid]       = d0 * rstd * g[tid] + b[tid];
    out[tok * DHID + tid + 256] = d1 * rstd * g[tid + 256] + b[tid + 256];
}

// ---------------- attention per (b, head): RoPE + causal softmax ----------------
__global__ void attn_kernel(const float* __restrict__ kqv, float* __restrict__ out) {
    __shared__ float q[32][64];
    __shared__ float k[32][65];
    __shared__ float v[32][64];
    __shared__ float s[32][33];
    int bh = blockIdx.x;
    int b = bh >> 3, h = bh & 7;
    int tid = threadIdx.x;

#pragma unroll
    for (int i = 0; i < 8; i++) {
        int e = tid + i * 256;
        int t = e >> 6, d = e & 63;
        const float* base = kqv + (long)(b * 32 + t) * 1536 + h * 64;
        float kk = base[d];
        float qq = base[512 + d];
        v[t][d] = base[1024 + d];
        int j = d & 31;
        float ang = (float)t * powf(10000.f, -(float)j * (1.f / 32.f));
        float sn, cs;
        sincosf(ang, &sn, &cs);
        if (d < 32) {
            float kp = base[d + 32], qp = base[512 + d + 32];
            k[t][d] = kk * cs - kp * sn;
            q[t][d] = qq * cs - qp * sn;
        } else {
            float kp = base[d - 32], qp = base[512 + d - 32];
            k[t][d] = kk * cs + kp * sn;
            q[t][d] = qq * cs + qp * sn;
        }
    }
    __syncthreads();
#pragma unroll
    for (int i = 0; i < 4; i++) {
        int e = tid + i * 256;
        int tq = e >> 5, tk = e & 31;
        if (tk <= tq) {
            float acc = 0.f;
#pragma unroll
            for (int dd = 0; dd < 64; dd++) acc += q[tq][dd] * k[tk][dd];
            s[tq][tk] = acc * 0.125f;
        }
    }
    __syncthreads();
    int wid = tid >> 5, lane = tid & 31;
    for (int r = wid; r < 32; r += 8) {
        float val = (lane <= r) ? s[r][lane] : -3.4e38f;
        float m = warp_max(val);
        float e = (lane <= r) ? expf(val - m) : 0.f;
        float sum = warp_sum(e);
        s[r][lane] = e / sum;
    }
    __syncthreads();
#pragma unroll
    for (int i = 0; i < 8; i++) {
        int e = tid + i * 256;
        int t = e >> 6, d = e & 63;
        float acc = 0.f;
#pragma unroll
        for (int kk2 = 0; kk2 < 32; kk2++) acc += s[t][kk2] * v[kk2][d];
        out[(long)(b * 32 + t) * DHID + h * 64 + d] = acc;
    }
}

// ---------------- head: LN + dot(head_w) ----------------
__global__ void head_kernel(const float* __restrict__ hin, const float* __restrict__ g,
                            const float* __restrict__ b, const float* __restrict__ w,
                            const float* __restrict__ bias0, float* __restrict__ out) {
    __shared__ float sbuf[8];
    int tok = blockIdx.x, tid = threadIdx.x;
    const float* row = hin + tok * DHID;
    float v0 = row[tid], v1 = row[tid + 256];
    float sum = block_sum_256(v0 + v1, sbuf);
    float mu = sum * (1.f / 512.f);
    float d0 = v0 - mu, d1 = v1 - mu;
    float vs = block_sum_256(d0 * d0 + d1 * d1, sbuf);
    float rstd = rsqrtf(vs * (1.f / 512.f) + 1e-5f);
    float c = (d0 * rstd * g[tid] + b[tid]) * w[tid] +
              (d1 * rstd * g[tid + 256] + b[tid + 256]) * w[tid + 256];
    float tot = block_sum_256(c, sbuf);
    if (tid == 0) out[tok] = tot + bias0[0];
}

// ---------------- launch ----------------
extern "C" void kernel_launch(void* const* d_in, const int* in_sizes, int n_in,
                              void* d_out, int out_size) {
    const float* x       = (const float*)d_in[0];
    const float* z       = (const float*)d_in[1];
    const float* conv_w  = (const float*)d_in[2];
    const float* conv_b  = (const float*)d_in[3];
    const float* tok_g   = (const float*)d_in[4];
    const float* tok_b   = (const float*)d_in[5];
    const float* film_w  = (const float*)d_in[6];
    const float* film_b  = (const float*)d_in[7];
    const float* ln1_g   = (const float*)d_in[8];
    const float* ln1_b   = (const float*)d_in[9];
    const float* kqv_w   = (const float*)d_in[10];
    const float* kqv_b   = (const float*)d_in[11];
    const float* proj_w  = (const float*)d_in[12];
    const float* proj_b  = (const float*)d_in[13];
    const float* ln2_g   = (const float*)d_in[14];
    const float* ln2_b   = (const float*)d_in[15];
    const float* mlp_w1  = (const float*)d_in[16];
    const float* mlp_b1  = (const float*)d_in[17];
    const float* mlp_w2  = (const float*)d_in[18];
    const float* mlp_b2  = (const float*)d_in[19];
    const float* rs_attn = (const float*)d_in[20];
    const float* rs_mlp  = (const float*)d_in[21];
    const float* head_g  = (const float*)d_in[22];
    const float* head_b  = (const float*)d_in[23];
    const float* head_w  = (const float*)d_in[24];
    const float* head_bi = (const float*)d_in[25];
    float* out = (float*)d_out;

    float *wT, *patches, *tok, *film, *h, *xln, *kqv, *attn, *mlp;
    cudaGetSymbolAddress((void**)&wT, g_wT);
    cudaGetSymbolAddress((void**)&patches, g_patches);
    cudaGetSymbolAddress((void**)&tok, g_tok);
    cudaGetSymbolAddress((void**)&film, g_film);
    cudaGetSymbolAddress((void**)&h, g_h);
    cudaGetSymbolAddress((void**)&xln, g_xln);
    cudaGetSymbolAddress((void**)&kqv, g_kqv);
    cudaGetSymbolAddress((void**)&attn, g_attn);
    cudaGetSymbolAddress((void**)&mlp, g_mlp);

    // tokenizer
    transpose_w_kernel<<<(DHID * KCONV + 255) / 256, 256>>>(conv_w, wT);
    im2col_kernel<<<(MCONV * KCONV + 255) / 256, 256>>>(x, patches);
    gemm_kernel<<<dim3(DHID / 64, MCONV / 64), 256>>>(patches, wT, conv_b, tok,
                                                      MCONV, DHID, KCONV, 0, nullptr, nullptr);
    // FiLM params
    gemm_kernel<<<dim3(1024 / 64, BT / 64), 256>>>(z, film_w, film_b, film,
                                                   BT, 1024, 32, 0, nullptr, nullptr);
    // token LN + FiLM + spatial mean
    tok_reduce_kernel<<<BT, 256>>>(tok, tok_g, tok_b, film, h);

    // transformer stack
    for (int i = 0; i < LAYERS; i++) {
        ln_kernel<<<BT, 256>>>(h, ln1_g + i * DHID, ln1_b + i * DHID, xln);
        gemm_kernel<<<dim3(1536 / 64, BT / 64), 256>>>(xln, kqv_w + (long)i * DHID * 1536,
                                                       kqv_b + i * 1536, kqv,
                                                       BT, 1536, DHID, 0, nullptr, nullptr);
        attn_kernel<<<BB * NHEAD, 256>>>(kqv, attn);
        gemm_kernel<<<dim3(DHID / 64, BT / 64), 256>>>(attn, proj_w + (long)i * DHID * DHID,
                                                       proj_b + i * DHID, h,
                                                       BT, DHID, DHID, 2, h, rs_attn + i);
        ln_kernel<<<BT, 256>>>(h, ln2_g + i * DHID, ln2_b + i * DHID, xln);
        gemm_kernel<<<dim3(2048 / 64, BT / 64), 256>>>(xln, mlp_w1 + (long)i * DHID * 2048,
                                                       mlp_b1 + i * 2048, mlp,
                                                       BT, 2048, DHID, 1, nullptr, nullptr);
        gemm_kernel<<<dim3(DHID / 64, BT / 64), 256>>>(mlp, mlp_w2 + (long)i * 2048 * DHID,
                                                       mlp_b2 + i * DHID, h,
                                                       BT, DHID, 2048, 2, h, rs_mlp + i);
    }
    // score head
    head_kernel<<<BT, 256>>>(h, head_g, head_b, head_w, head_bi, out);
}

// round 3
// speedup vs baseline: 2.8690x; 2.8690x over previous
#include <cuda_runtime.h>
#include <cuda_fp16.h>
#include <cstdint>
#include <math.h>

// ---------------- problem constants ----------------
#define DHID   512
#define NHEAD  8
#define LAYERS 6
#define BB     16
#define TT     32
#define NTOK   64
#define KCONV  576
#define BT     512
#define MCONV  32768

// ---------------- device scratch ----------------
__device__ __half g_wT_h[KCONV * DHID];
__device__ __half g_patch_h[(size_t)MCONV * KCONV];
__device__ __half g_kqvw_h[LAYERS * DHID * 3 * DHID];
__device__ __half g_projw_h[LAYERS * DHID * DHID];
__device__ __half g_w1_h[LAYERS * DHID * 4 * DHID];
__device__ __half g_w2_h[LAYERS * 4 * DHID * DHID];
__device__ __half g_xln_h[BT * DHID];
__device__ __half g_attn_h[BT * DHID];
__device__ __half g_mlp_h[BT * 4 * DHID];
__device__ float  g_tok[(size_t)MCONV * DHID];
__device__ float  g_film[BT * 2 * DHID];
__device__ float  g_h[BT * DHID];
__device__ float  g_kqv[BT * 3 * DHID];

// ---------------- helpers ----------------
__device__ __forceinline__ float warp_sum(float v) {
#pragma unroll
    for (int o = 16; o; o >>= 1) v += __shfl_xor_sync(0xffffffffu, v, o);
    return v;
}
__device__ __forceinline__ float warp_max(float v) {
#pragma unroll
    for (int o = 16; o; o >>= 1) v = fmaxf(v, __shfl_xor_sync(0xffffffffu, v, o));
    return v;
}
__device__ __forceinline__ float block_sum_256(float v, float* sbuf) {
    int lane = threadIdx.x & 31, wid = threadIdx.x >> 5;
    v = warp_sum(v);
    if (lane == 0) sbuf[wid] = v;
    __syncthreads();
    float r = sbuf[0];
#pragma unroll
    for (int w = 1; w < 8; w++) r += sbuf[w];
    __syncthreads();
    return r;
}
__device__ __forceinline__ unsigned smem_u32(const void* p) {
    return (unsigned)__cvta_generic_to_shared(p);
}

// ---------------- conversions ----------------
__global__ void f2h_kernel(const float4* __restrict__ s, __half* __restrict__ d, int n4) {
    int i = blockIdx.x * 256 + threadIdx.x;
    if (i >= n4) return;
    float4 v = s[i];
    __half2* o = (__half2*)(d + i * 4);
    o[0] = __floats2half2_rn(v.x, v.y);
    o[1] = __floats2half2_rn(v.z, v.w);
}
__global__ void transpose_wh_kernel(const float* __restrict__ w, __half* __restrict__ wT) {
    int idx = blockIdx.x * 256 + threadIdx.x;
    if (idx >= DHID * KCONV) return;
    int d = idx / KCONV, k = idx % KCONV;
    wT[k * DHID + d] = __float2half_rn(w[idx]);
}

// ---------------- im2col (causal time pad 2) -> fp16 ----------------
__global__ void im2col_kernel(const float* __restrict__ x, __half* __restrict__ p) {
    long idx = (long)blockIdx.x * 256 + threadIdx.x;
    if (idx >= (long)MCONV * KCONV) return;
    int kcol = (int)(idx % KCONV);
    long row = idx / KCONV;
    int n  = (int)(row & 63);
    int bt = (int)(row >> 6);
    int t  = bt & 31;
    int b  = bt >> 5;
    int hn = n >> 3, wn = n & 7;
    int pw = kcol & 7;
    int ph = (kcol >> 3) & 7;
    int kt = (kcol >> 6) % 3;
    int c  = kcol / 192;
    int tt = t + kt - 2;
    float v = 0.f;
    if (tt >= 0)
        v = x[((((long)(b * 32 + tt) * 3 + c) * 64) + hn * 8 + ph) * 64 + wn * 8 + pw];
    p[idx] = __float2half_rn(v);
}

// ---------------- tensor-core GEMM ----------------
// C[M,N] = epi( A[M,K](fp16) * B[K,N](fp16) + bias )
// epi 0: Cf = acc+bias (fp32)
// epi 1: Ch = half(gelu(acc+bias))
// epi 2: Cf = res + scale[0]*(acc+bias)   (res may alias Cf)
#define APAD 8
#define BPAD 8

template<int BM, int BN, int WM, int WN>
__global__ void hgemm_kernel(const __half* __restrict__ A, const __half* __restrict__ B,
                             const float* __restrict__ bias,
                             float* __restrict__ Cf, __half* __restrict__ Ch,
                             int M, int N, int K, int epi,
                             const float* __restrict__ res, const float* __restrict__ scale) {
    constexpr int NT = WM * WN * 32;
    constexpr int A_IT = BM * 4 / NT;
    constexpr int B_IT = 4 * BN / NT;
    __shared__ __half As[2][BM][32 + APAD];
    __shared__ __half Bs[2][32][BN + BPAD];

    int tid = threadIdx.x;
    int lane = tid & 31;
    int warp = tid >> 5;
    int wm = warp / WN, wn = warp % WN;
    int bm = blockIdx.y * BM, bn = blockIdx.x * BN;
    int KT = K >> 5;

    float c[2][4][4];
#pragma unroll
    for (int i = 0; i < 2; i++)
#pragma unroll
        for (int j = 0; j < 4; j++)
#pragma unroll
            for (int e = 0; e < 4; e++) c[i][j][e] = 0.f;

    // load tile 0
#pragma unroll
    for (int i = 0; i < A_IT; i++) {
        int u = tid + i * NT; int r = u >> 2, q = u & 3;
        *(uint4*)&As[0][r][q * 8] = *(const uint4*)(A + (long)(bm + r) * K + q * 8);
    }
#pragma unroll
    for (int i = 0; i < B_IT; i++) {
        int v = tid + i * NT; int r = v / (BN / 8), q = v % (BN / 8);
        *(uint4*)&Bs[0][r][q * 8] = *(const uint4*)(B + (long)r * N + bn + q * 8);
    }
    __syncthreads();

    for (int kt = 0; kt < KT; kt++) {
        uint4 pa[A_IT]; uint4 pb[B_IT];
        bool more = (kt + 1 < KT);
        if (more) {
            int k0 = (kt + 1) * 32;
#pragma unroll
            for (int i = 0; i < A_IT; i++) {
                int u = tid + i * NT; int r = u >> 2, q = u & 3;
                pa[i] = *(const uint4*)(A + (long)(bm + r) * K + k0 + q * 8);
            }
#pragma unroll
            for (int i = 0; i < B_IT; i++) {
                int v = tid + i * NT; int r = v / (BN / 8), q = v % (BN / 8);
                pb[i] = *(const uint4*)(B + (long)(k0 + r) * N + bn + q * 8);
            }
        }
        int buf = kt & 1;
#pragma unroll
        for (int ks = 0; ks < 32; ks += 16) {
            unsigned a[2][4], bf[2][4];
#pragma unroll
            for (int i = 0; i < 2; i++) {
                unsigned addr = smem_u32(&As[buf][wm * 32 + i * 16 + (lane & 15)][ks + (lane >> 4) * 8]);
                asm volatile("ldmatrix.sync.aligned.m8n8.x4.shared.b16 {%0,%1,%2,%3}, [%4];"
                             : "=r"(a[i][0]), "=r"(a[i][1]), "=r"(a[i][2]), "=r"(a[i][3]) : "r"(addr));
            }
#pragma unroll
            for (int j2 = 0; j2 < 2; j2++) {
                unsigned addr = smem_u32(&Bs[buf][ks + (lane & 7) + ((lane >> 3) & 1) * 8]
                                             [wn * 32 + j2 * 16 + (lane >> 4) * 8]);
                asm volatile("ldmatrix.sync.aligned.m8n8.x4.trans.shared.b16 {%0,%1,%2,%3}, [%4];"
                             : "=r"(bf[j2][0]), "=r"(bf[j2][1]), "=r"(bf[j2][2]), "=r"(bf[j2][3]) : "r"(addr));
            }
#pragma unroll
            for (int i = 0; i < 2; i++)
#pragma unroll
                for (int j = 0; j < 4; j++) {
                    unsigned b0 = bf[j >> 1][(j & 1) * 2], b1 = bf[j >> 1][(j & 1) * 2 + 1];
                    asm volatile(
                        "mma.sync.aligned.m16n8k16.row.col.f32.f16.f16.f32 "
                        "{%0,%1,%2,%3}, {%4,%5,%6,%7}, {%8,%9}, {%0,%1,%2,%3};"
                        : "+f"(c[i][j][0]), "+f"(c[i][j][1]), "+f"(c[i][j][2]), "+f"(c[i][j][3])
                        : "r"(a[i][0]), "r"(a[i][1]), "r"(a[i][2]), "r"(a[i][3]), "r"(b0), "r"(b1));
                }
        }
        if (more) {
            int nb = buf ^ 1;
#pragma unroll
            for (int i = 0; i < A_IT; i++) {
                int u = tid + i * NT; int r = u >> 2, q = u & 3;
                *(uint4*)&As[nb][r][q * 8] = pa[i];
            }
#pragma unroll
            for (int i = 0; i < B_IT; i++) {
                int v = tid + i * NT; int r = v / (BN / 8), q = v % (BN / 8);
                *(uint4*)&Bs[nb][r][q * 8] = pb[i];
            }
        }
        __syncthreads();
    }

    // epilogue
    float sc = (epi == 2) ? scale[0] : 0.f;
#pragma unroll
    for (int i = 0; i < 2; i++)
#pragma unroll
        for (int j = 0; j < 4; j++) {
            int r0 = bm + wm * 32 + i * 16 + (lane >> 2);
            int c0 = bn + wn * 32 + j * 8 + (lane & 3) * 2;
#pragma unroll
            for (int half_ = 0; half_ < 2; half_++) {
                int rr = r0 + half_ * 8;
                float v0 = c[i][j][half_ * 2 + 0] + bias[c0];
                float v1 = c[i][j][half_ * 2 + 1] + bias[c0 + 1];
                long off = (long)rr * N + c0;
                if (epi == 0) {
                    *(float2*)&Cf[off] = make_float2(v0, v1);
                } else if (epi == 1) {
                    float g0 = 0.5f * v0 * (1.f + erff(v0 * 0.70710678118654752f));
                    float g1 = 0.5f * v1 * (1.f + erff(v1 * 0.70710678118654752f));
                    *(__half2*)&Ch[off] = __floats2half2_rn(g0, g1);
                } else {
                    float2 rv = *(const float2*)&res[off];
                    *(float2*)&Cf[off] = make_float2(rv.x + sc * v0, rv.y + sc * v1);
                }
            }
        }
}

// ---------------- small fp32 GEMM (film only) ----------------
__global__ void gemm_kernel(const float* __restrict__ A, const float* __restrict__ Bm,
                            const float* __restrict__ bias, float* C,
                            int M, int N, int K) {
    __shared__ float As[16][65];
    __shared__ float Bs[16][64];
    int bm = blockIdx.y * 64, bn = blockIdx.x * 64;
    int tid = threadIdx.x;
    int tx = tid & 15, ty = tid >> 4;
    float acc[4][4];
#pragma unroll
    for (int i = 0; i < 4; i++)
#pragma unroll
        for (int j = 0; j < 4; j++) acc[i][j] = 0.f;
    const float* Ab = A + (long)bm * K;
    for (int k0 = 0; k0 < K; k0 += 16) {
        {
            int col = tid & 15, row = tid >> 4;
#pragma unroll
            for (int r = 0; r < 4; r++)
                As[col][row + r * 16] = Ab[(long)(row + r * 16) * K + k0 + col];
        }
        {
            int col = tid & 63, row = tid >> 6;
#pragma unroll
            for (int r = 0; r < 4; r++)
                Bs[row + r * 4][col] = Bm[(long)(k0 + row + r * 4) * N + bn + col];
        }
        __syncthreads();
#pragma unroll
        for (int kk = 0; kk < 16; kk++) {
            float a0 = As[kk][ty * 4 + 0], a1 = As[kk][ty * 4 + 1];
            float a2 = As[kk][ty * 4 + 2], a3 = As[kk][ty * 4 + 3];
            float4 b4 = *(const float4*)&Bs[kk][tx * 4];
            acc[0][0] += a0 * b4.x; acc[0][1] += a0 * b4.y; acc[0][2] += a0 * b4.z; acc[0][3] += a0 * b4.w;
            acc[1][0] += a1 * b4.x; acc[1][1] += a1 * b4.y; acc[1][2] += a1 * b4.z; acc[1][3] += a1 * b4.w;
            acc[2][0] += a2 * b4.x; acc[2][1] += a2 * b4.y; acc[2][2] += a2 * b4.z; acc[2][3] += a2 * b4.w;
            acc[3][0] += a3 * b4.x; acc[3][1] += a3 * b4.y; acc[3][2] += a3 * b4.z; acc[3][3] += a3 * b4.w;
        }
        __syncthreads();
    }
#pragma unroll
    for (int i = 0; i < 4; i++) {
        int row = bm + ty * 4 + i;
#pragma unroll
        for (int j = 0; j < 4; j++) {
            int col = bn + tx * 4 + j;
            C[(long)row * N + col] = acc[i][j] + bias[col];
        }
    }
}

// ---------------- fused token LN + FiLM + spatial mean ----------------
__global__ void tok_reduce_kernel(const float* __restrict__ tok, const float* __restrict__ tg,
                                  const float* __restrict__ tb, const float* __restrict__ film,
                                  float* __restrict__ h) {
    __shared__ float accs[8][DHID];
    int bt = blockIdx.x;
    int wid = threadIdx.x >> 5, lane = threadIdx.x & 31;
    float acc[16];
#pragma unroll
    for (int i = 0; i < 16; i++) acc[i] = 0.f;
    const float* gb = film + bt * (2 * DHID);
    for (int n = wid; n < NTOK; n += 8) {
        const float* row = tok + (long)(bt * NTOK + n) * DHID;
        float v[16]; float s = 0.f;
#pragma unroll
        for (int i = 0; i < 16; i++) { v[i] = row[i * 32 + lane]; s += v[i]; }
        s = warp_sum(s);
        float mu = s * (1.f / 512.f);
        float vs = 0.f;
#pragma unroll
        for (int i = 0; i < 16; i++) { float d = v[i] - mu; vs += d * d; }
        vs = warp_sum(vs);
        float rstd = rsqrtf(vs * (1.f / 512.f) + 1e-5f);
#pragma unroll
        for (int i = 0; i < 16; i++) {
            int d = i * 32 + lane;
            float ln = (v[i] - mu) * rstd * tg[d] + tb[d];
            acc[i] += (1.f + 0.5f * gb[d]) * ln + 0.5f * gb[DHID + d];
        }
    }
#pragma unroll
    for (int i = 0; i < 16; i++) accs[wid][i * 32 + lane] = acc[i];
    __syncthreads();
    for (int d = threadIdx.x; d < DHID; d += 256) {
        float s = 0.f;
#pragma unroll
        for (int w = 0; w < 8; w++) s += accs[w][d];
        h[bt * DHID + d] = s * (1.f / 64.f);
    }
}

// ---------------- LayerNorm -> fp16 out ----------------
__global__ void ln_h_kernel(const float* __restrict__ in, const float* __restrict__ g,
                            const float* __restrict__ b, __half* __restrict__ out) {
    __shared__ float sbuf[8];
    int tok = blockIdx.x, tid = threadIdx.x;
    const float* row = in + tok * DHID;
    float v0 = row[tid], v1 = row[tid + 256];
    float sum = block_sum_256(v0 + v1, sbuf);
    float mu = sum * (1.f / 512.f);
    float d0 = v0 - mu, d1 = v1 - mu;
    float vs = block_sum_256(d0 * d0 + d1 * d1, sbuf);
    float rstd = rsqrtf(vs * (1.f / 512.f) + 1e-5f);
    out[tok * DHID + tid]       = __float2half_rn(d0 * rstd * g[tid] + b[tid]);
    out[tok * DHID + tid + 256] = __float2half_rn(d1 * rstd * g[tid + 256] + b[tid + 256]);
}

// ---------------- attention per (b, head) ----------------
__global__ void attn_kernel(const float* __restrict__ kqv, __half* __restrict__ out) {
    __shared__ float q[32][64];
    __shared__ float k[32][65];
    __shared__ float v[32][64];
    __shared__ float s[32][33];
    int bh = blockIdx.x;
    int b = bh >> 3, h = bh & 7;
    int tid = threadIdx.x;
#pragma unroll
    for (int i = 0; i < 8; i++) {
        int e = tid + i * 256;
        int t = e >> 6, d = e & 63;
        const float* base = kqv + (long)(b * 32 + t) * 1536 + h * 64;
        float kk = base[d];
        float qq = base[512 + d];
        v[t][d] = base[1024 + d];
        int j = d & 31;
        float ang = (float)t * powf(10000.f, -(float)j * (1.f / 32.f));
        float sn, cs;
        sincosf(ang, &sn, &cs);
        if (d < 32) {
            float kp = base[d + 32], qp = base[512 + d + 32];
            k[t][d] = kk * cs - kp * sn;
            q[t][d] = qq * cs - qp * sn;
        } else {
            float kp = base[d - 32], qp = base[512 + d - 32];
            k[t][d] = kk * cs + kp * sn;
            q[t][d] = qq * cs + qp * sn;
        }
    }
    __syncthreads();
#pragma unroll
    for (int i = 0; i < 4; i++) {
        int e = tid + i * 256;
        int tq = e >> 5, tk = e & 31;
        if (tk <= tq) {
            float acc = 0.f;
#pragma unroll
            for (int dd = 0; dd < 64; dd++) acc += q[tq][dd] * k[tk][dd];
            s[tq][tk] = acc * 0.125f;
        }
    }
    __syncthreads();
    int wid = tid >> 5, lane = tid & 31;
    for (int r = wid; r < 32; r += 8) {
        float val = (lane <= r) ? s[r][lane] : -3.4e38f;
        float m = warp_max(val);
        float e = (lane <= r) ? expf(val - m) : 0.f;
        float sum = warp_sum(e);
        s[r][lane] = e / sum;
    }
    __syncthreads();
#pragma unroll
    for (int i = 0; i < 8; i++) {
        int e = tid + i * 256;
        int t = e >> 6, d = e & 63;
        float acc = 0.f;
#pragma unroll
        for (int kk2 = 0; kk2 < 32; kk2++) acc += s[t][kk2] * v[kk2][d];
        out[(long)(b * 32 + t) * DHID + h * 64 + d] = __float2half_rn(acc);
    }
}

// ---------------- head ----------------
__global__ void head_kernel(const float* __restrict__ hin, const float* __restrict__ g,
                            const float* __restrict__ b, const float* __restrict__ w,
                            const float* __restrict__ bias0, float* __restrict__ out) {
    __shared__ float sbuf[8];
    int tok = blockIdx.x, tid = threadIdx.x;
    const float* row = hin + tok * DHID;
    float v0 = row[tid], v1 = row[tid + 256];
    float sum = block_sum_256(v0 + v1, sbuf);
    float mu = sum * (1.f / 512.f);
    float d0 = v0 - mu, d1 = v1 - mu;
    float vs = block_sum_256(d0 * d0 + d1 * d1, sbuf);
    float rstd = rsqrtf(vs * (1.f / 512.f) + 1e-5f);
    float c = (d0 * rstd * g[tid] + b[tid]) * w[tid] +
              (d1 * rstd * g[tid + 256] + b[tid + 256]) * w[tid + 256];
    float tot = block_sum_256(c, sbuf);
    if (tid == 0) out[tok] = tot + bias0[0];
}

// ---------------- launch ----------------
extern "C" void kernel_launch(void* const* d_in, const int* in_sizes, int n_in,
                              void* d_out, int out_size) {
    const float* x       = (const float*)d_in[0];
    const float* z       = (const float*)d_in[1];
    const float* conv_w  = (const float*)d_in[2];
    const float* conv_b  = (const float*)d_in[3];
    const float* tok_g   = (const float*)d_in[4];
    const float* tok_b   = (const float*)d_in[5];
    const float* film_w  = (const float*)d_in[6];
    const float* film_b  = (const float*)d_in[7];
    const float* ln1_g   = (const float*)d_in[8];
    const float* ln1_b   = (const float*)d_in[9];
    const float* kqv_w   = (const float*)d_in[10];
    const float* kqv_b   = (const float*)d_in[11];
    const float* proj_w  = (const float*)d_in[12];
    const float* proj_b  = (const float*)d_in[13];
    const float* ln2_g   = (const float*)d_in[14];
    const float* ln2_b   = (const float*)d_in[15];
    const float* mlp_w1  = (const float*)d_in[16];
    const float* mlp_b1  = (const float*)d_in[17];
    const float* mlp_w2  = (const float*)d_in[18];
    const float* mlp_b2  = (const float*)d_in[19];
    const float* rs_attn = (const float*)d_in[20];
    const float* rs_mlp  = (const float*)d_in[21];
    const float* head_g  = (const float*)d_in[22];
    const float* head_b  = (const float*)d_in[23];
    const float* head_w  = (const float*)d_in[24];
    const float* head_bi = (const float*)d_in[25];
    float* out = (float*)d_out;

    __half *wT_h, *patch_h, *kqvw_h, *projw_h, *w1_h, *w2_h, *xln_h, *attn_h, *mlp_h;
    float *tok, *film, *h, *kqv;
    cudaGetSymbolAddress((void**)&wT_h, g_wT_h);
    cudaGetSymbolAddress((void**)&patch_h, g_patch_h);
    cudaGetSymbolAddress((void**)&kqvw_h, g_kqvw_h);
    cudaGetSymbolAddress((void**)&projw_h, g_projw_h);
    cudaGetSymbolAddress((void**)&w1_h, g_w1_h);
    cudaGetSymbolAddress((void**)&w2_h, g_w2_h);
    cudaGetSymbolAddress((void**)&xln_h, g_xln_h);
    cudaGetSymbolAddress((void**)&attn_h, g_attn_h);
    cudaGetSymbolAddress((void**)&mlp_h, g_mlp_h);
    cudaGetSymbolAddress((void**)&tok, g_tok);
    cudaGetSymbolAddress((void**)&film, g_film);
    cudaGetSymbolAddress((void**)&h, g_h);
    cudaGetSymbolAddress((void**)&kqv, g_kqv);

    // weight conversions
    transpose_wh_kernel<<<(DHID * KCONV + 255) / 256, 256>>>(conv_w, wT_h);
    {
        int n;
        n = LAYERS * DHID * 3 * DHID / 4;
        f2h_kernel<<<(n + 255) / 256, 256>>>((const float4*)kqv_w, kqvw_h, n);
        n = LAYERS * DHID * DHID / 4;
        f2h_kernel<<<(n + 255) / 256, 256>>>((const float4*)proj_w, projw_h, n);
        n = LAYERS * DHID * 4 * DHID / 4;
        f2h_kernel<<<(n + 255) / 256, 256>>>((const float4*)mlp_w1, w1_h, n);
        f2h_kernel<<<(n + 255) / 256, 256>>>((const float4*)mlp_w2, w2_h, n);
    }
    // tokenizer
    im2col_kernel<<<(int)(((long)MCONV * KCONV + 255) / 256), 256>>>(x, patch_h);
    hgemm_kernel<128, 64, 4, 2><<<dim3(DHID / 64, MCONV / 128), 256>>>(
        patch_h, wT_h, conv_b, tok, nullptr, MCONV, DHID, KCONV, 0, nullptr, nullptr);
    // FiLM params (tiny fp32 GEMM)
    gemm_kernel<<<dim3(1024 / 64, BT / 64), 256>>>(z, film_w, film_b, film, BT, 1024, 32);
    tok_reduce_kernel<<<BT, 256>>>(tok, tok_g, tok_b, film, h);

    // transformer
    for (int i = 0; i < LAYERS; i++) {
        ln_h_kernel<<<BT, 256>>>(h, ln1_g + i * DHID, ln1_b + i * DHID, xln_h);
        hgemm_kernel<64, 64, 2, 2><<<dim3(1536 / 64, BT / 64), 128>>>(
            xln_h, kqvw_h + (long)i * DHID * 1536, kqv_b + i * 1536, kqv, nullptr,
            BT, 1536, DHID, 0, nullptr, nullptr);
        attn_kernel<<<BB * NHEAD, 256>>>(kqv, attn_h);
        hgemm_kernel<64, 64, 2, 2><<<dim3(DHID / 64, BT / 64), 128>>>(
            attn_h, projw_h + (long)i * DHID * DHID, proj_b + i * DHID, h, nullptr,
            BT, DHID, DHID, 2, h, rs_attn + i);
        ln_h_kernel<<<BT, 256>>>(h, ln2_g + i * DHID, ln2_b + i * DHID, xln_h);
        hgemm_kernel<64, 64, 2, 2><<<dim3(2048 / 64, BT / 64), 128>>>(
            xln_h, w1_h + (long)i * DHID * 2048, mlp_b1 + i * 2048, nullptr, mlp_h,
            BT, 2048, DHID, 1, nullptr, nullptr);
        hgemm_kernel<64, 64, 2, 2><<<dim3(DHID / 64, BT / 64), 128>>>(
            mlp_h, w2_h + (long)i * 2048 * DHID, mlp_b2 + i * DHID, h, nullptr,
            BT, DHID, 2048, 2, h, rs_mlp + i);
    }
    head_kernel<<<BT, 256>>>(h, head_g, head_b, head_w, head_bi, out);
}